// round 9
// baseline (speedup 1.0000x reference)
#include <cuda_runtime.h>
#include <cstdint>
#include <cstddef>

#define EPSV 1e-5f

// g_q/g_k: [(s*32+c)*256 + b]  — GEMM1 operand rows (m=(s,c)), K(=b)-contiguous
__device__ float g_q[384 * 32 * 256];
__device__ float g_k[384 * 32 * 256];
// g_wo: 32 k-slices, each the ready smem image: [n=128][32 floats, XOR-swizzled]
__device__ float g_wo[32 * 4096];
// g_a: [p = i*384+j][e = c*32+d]  row-major — GEMM2 A operand
__device__ float g_a[150994944];  // 147456 * 1024 floats = 604 MB

// ---------------- helpers ----------------
__device__ __forceinline__ uint32_t smem_u32(const void* p) {
    uint32_t a;
    asm("{ .reg .u64 t; cvta.to.shared.u64 t, %1; cvt.u32.u64 %0, t; }" : "=r"(a) : "l"(p));
    return a;
}
__device__ __forceinline__ float f2tf32(float x) {
    uint32_t r;
    asm("cvt.rna.tf32.f32 %0, %1;" : "=r"(r) : "f"(x));
    return __uint_as_float(r);
}
#define CP_ASYNC16(dst, src) \
    asm volatile("cp.async.cg.shared.global [%0], [%1], 16;" :: "r"(dst), "l"(src))
#define CP_COMMIT() asm volatile("cp.async.commit_group;")
#define CP_WAIT1()  asm volatile("cp.async.wait_group 1;")
#define CP_WAIT0()  asm volatile("cp.async.wait_group 0;")

#define LDSM_X4(r0, r1, r2, r3, addr) \
    asm volatile("ldmatrix.sync.aligned.m8n8.x4.shared.b16 {%0,%1,%2,%3}, [%4];" \
                 : "=r"(r0), "=r"(r1), "=r"(r2), "=r"(r3) : "r"(addr))

__device__ __forceinline__ void mma_tf32(float* d, uint32_t a0, uint32_t a1,
                                         uint32_t a2, uint32_t a3,
                                         uint32_t b0, uint32_t b1) {
    asm volatile(
        "mma.sync.aligned.m16n8k8.row.col.f32.tf32.tf32.f32 "
        "{%0,%1,%2,%3}, {%4,%5,%6,%7}, {%8,%9}, {%0,%1,%2,%3};"
        : "+f"(d[0]), "+f"(d[1]), "+f"(d[2]), "+f"(d[3])
        : "r"(a0), "r"(a1), "r"(a2), "r"(a3), "r"(b0), "r"(b1));
}

// ============================================================================
// proj: rmsnorm(m)*g_in -> q/k projections -> tf32-rounded transposed store
// ============================================================================
__global__ __launch_bounds__(256, 2)
void proj_kernel(const float* __restrict__ m, const float* __restrict__ g_in,
                 const float* __restrict__ Wq, const float* __restrict__ bq,
                 const float* __restrict__ Wk, const float* __restrict__ bk)
{
    extern __shared__ float sm[];
    float* Wq_s = sm;
    float* Wk_s = sm + 8192;
    float* mn_s = sm + 16384;
    const int tid = threadIdx.x, warp = tid >> 5, lane = tid & 31;
    const float4* Wq4 = (const float4*)Wq;
    const float4* Wk4 = (const float4*)Wk;
#pragma unroll
    for (int v = 0; v < 8; ++v) {
        ((float4*)Wq_s)[v * 256 + tid] = Wq4[v * 256 + tid];
        ((float4*)Wk_s)[v * 256 + tid] = Wk4[v * 256 + tid];
    }
    const int rb = (blockIdx.x * 8 + warp) * 4;
    float* mw = mn_s + warp * 1024;
    const float4 gi0 = ((const float4*)g_in)[lane * 2];
    const float4 gi1 = ((const float4*)g_in)[lane * 2 + 1];
    float vals[4][8], ssum[4];
#pragma unroll
    for (int r = 0; r < 4; ++r) {
        const float4* mp = (const float4*)(m + (size_t)(rb + r) * 256);
        float4 a = mp[lane * 2], b = mp[lane * 2 + 1];
        vals[r][0] = a.x; vals[r][1] = a.y; vals[r][2] = a.z; vals[r][3] = a.w;
        vals[r][4] = b.x; vals[r][5] = b.y; vals[r][6] = b.z; vals[r][7] = b.w;
        ssum[r] = a.x*a.x + a.y*a.y + a.z*a.z + a.w*a.w
                + b.x*b.x + b.y*b.y + b.z*b.z + b.w*b.w;
    }
#pragma unroll
    for (int r = 0; r < 4; ++r) {
        float s = ssum[r];
#pragma unroll
        for (int o = 16; o >= 1; o >>= 1) s += __shfl_xor_sync(~0u, s, o);
        const float sc = rsqrtf(s * (1.0f / 256.0f) + EPSV);
        float4 o0, o1;
        o0.x = vals[r][0]*sc*gi0.x; o0.y = vals[r][1]*sc*gi0.y;
        o0.z = vals[r][2]*sc*gi0.z; o0.w = vals[r][3]*sc*gi0.w;
        o1.x = vals[r][4]*sc*gi1.x; o1.y = vals[r][5]*sc*gi1.y;
        o1.z = vals[r][6]*sc*gi1.z; o1.w = vals[r][7]*sc*gi1.w;
        ((float4*)(mw + r * 256))[lane * 2]     = o0;
        ((float4*)(mw + r * 256))[lane * 2 + 1] = o1;
    }
    __syncthreads();
    float aq[4], ak[4];
    const float bqv = __ldg(bq + lane), bkv = __ldg(bk + lane);
#pragma unroll
    for (int r = 0; r < 4; ++r) { aq[r] = bqv; ak[r] = bkv; }
#pragma unroll 4
    for (int mm = 0; mm < 256; ++mm) {
        const float wq = Wq_s[mm * 32 + lane], wk = Wk_s[mm * 32 + lane];
#pragma unroll
        for (int r = 0; r < 4; ++r) {
            const float x = mw[r * 256 + mm];
            aq[r] = fmaf(x, wq, aq[r]);
            ak[r] = fmaf(x, wk, ak[r]);
        }
    }
#pragma unroll
    for (int r = 0; r < 4; ++r) {
        const int row = rb + r, b = row / 384, s = row - b * 384;
        g_q[(size_t)(s * 32 + lane) * 256 + b] = f2tf32(aq[r]);
        g_k[(size_t)(s * 32 + lane) * 256 + b] = f2tf32(ak[r]);
    }
}

// ============================================================================
// wot: Wo[e=ks*32+kk][z=n] -> g_wo[ks][n*32 + swiz(kk,n)] (tf32-rounded)
// ============================================================================
__global__ void wot_kernel(const float* __restrict__ Wo) {
    const int ks = blockIdx.x, n = threadIdx.x;
    float* dst = g_wo + ks * 4096 + n * 32;
    const int n7 = n & 7;
#pragma unroll
    for (int kk = 0; kk < 32; ++kk) {
        const float v = f2tf32(__ldg(Wo + (size_t)(ks * 32 + kk) * 128 + n));
        dst[(((kk >> 2) ^ n7) << 2) | (kk & 3)] = v;
    }
}

// ============================================================================
// 512-thread GEMM machinery: 16 warps as 4x4, warp tile 32m x 32n.
// ============================================================================
struct LdsmAddrs { uint32_t a[2]; uint32_t b[2]; };

__device__ __forceinline__ LdsmAddrs ldsm_prep(int w, int l) {
    const int mw = w >> 2, nw = w & 3;
    const int r7 = l & 7;
    LdsmAddrs o;
    const int kbitA = (l >> 4) & 1;
    const int rhiA  = (l >> 3) & 1;
#pragma unroll
    for (int mi = 0; mi < 2; ++mi) {
        const int row = mw * 32 + mi * 16 + rhiA * 8 + r7;
        o.a[mi] = (uint32_t)(row * 128 + ((r7 ^ kbitA) << 4));
    }
    const int kbitB = (l >> 3) & 1;
    const int rhiB  = (l >> 4) & 1;
#pragma unroll
    for (int nip = 0; nip < 2; ++nip) {
        const int row = nw * 32 + nip * 16 + rhiB * 8 + r7;
        o.b[nip] = (uint32_t)(16384 + row * 128 + ((r7 ^ kbitB) << 4));
    }
    return o;
}

__device__ __forceinline__ void mma_chunk(uint32_t stage, const LdsmAddrs& ad,
                                          float acc[2][4][4]) {
#pragma unroll
    for (int s = 0; s < 4; ++s) {
        const uint32_t sx = (uint32_t)(s << 5);
        uint32_t b0[4], b1[4];
        LDSM_X4(b0[0], b1[0], b0[1], b1[1], stage + (ad.b[0] ^ sx));
        LDSM_X4(b0[2], b1[2], b0[3], b1[3], stage + (ad.b[1] ^ sx));
#pragma unroll
        for (int mi = 0; mi < 2; ++mi) {
            uint32_t A0, A1, A2, A3;
            LDSM_X4(A0, A1, A2, A3, stage + (ad.a[mi] ^ sx));
#pragma unroll
            for (int ni = 0; ni < 4; ++ni)
                mma_tf32(acc[mi][ni], A0, A1, A2, A3, b0[ni], b1[ni]);
        }
    }
}

// ============================================================================
// gemm1: D[(i,c)][(j,d)] = sum_b q*k — 128x128x256, 3-stage ring, 512 thr.
// Direct register->global scatter epilogue.
// ============================================================================
__global__ __launch_bounds__(512, 2)
void gemm1_kernel() {
    extern __shared__ float sm[];
    const int tid = threadIdx.x, w = tid >> 5, l = tid & 31;
    const int mw = w >> 2, nw = w & 3, lg = l >> 2, lm4 = l & 3;
    const int irow = blockIdx.y * 128, jrow = blockIdx.x * 128;
    const uint32_t smb = smem_u32(sm);
    const LdsmAddrs ad = ldsm_prep(w, l);

    float acc[2][4][4] = {};

    int srow[2], sq[2];
    uint32_t sdst[2];
#pragma unroll
    for (int v = 0; v < 2; ++v) {
        const int fl = v * 512 + tid;
        srow[v] = fl >> 3;
        sq[v]   = fl & 7;
        sdst[v] = (uint32_t)((srow[v] * 8 + (sq[v] ^ (srow[v] & 7))) * 16);
    }

#define G1_STAGE(ks, buf) do {                                                  \
    const uint32_t bofs = smb + (uint32_t)(buf) * 32768u;                       \
    _Pragma("unroll")                                                           \
    for (int v = 0; v < 2; ++v) {                                               \
        const float* sA = g_q + (size_t)(irow + srow[v]) * 256 + (ks) * 32 + sq[v] * 4; \
        const float* sB = g_k + (size_t)(jrow + srow[v]) * 256 + (ks) * 32 + sq[v] * 4; \
        CP_ASYNC16(bofs + sdst[v], sA);                                         \
        CP_ASYNC16(bofs + 16384 + sdst[v], sB);                                 \
    }                                                                           \
    CP_COMMIT();                                                                \
} while (0)

    G1_STAGE(0, 0);
    G1_STAGE(1, 1);
#pragma unroll
    for (int ks = 0; ks < 8; ++ks) {
        if (ks + 1 < 8) CP_WAIT1(); else CP_WAIT0();
        __syncthreads();
        if (ks + 2 < 8) G1_STAGE(ks + 2, (ks + 2) % 3);
        mma_chunk(smb + (uint32_t)(ks % 3) * 32768u, ad, acc);
    }

    // direct epilogue: r = mw*32 + mi*16 + half*8 + lg -> i=by*4+mw, c=r&31
    const int j = blockIdx.x * 4 + nw;
    const int i = blockIdx.y * 4 + mw;
#pragma unroll
    for (int mi = 0; mi < 2; ++mi) {
#pragma unroll
        for (int half = 0; half < 2; ++half) {
            const int c = mi * 16 + half * 8 + lg;
            float* base = g_a + (size_t)(i * 384 + j) * 1024 + c * 32 + lm4 * 2;
#pragma unroll
            for (int ni = 0; ni < 4; ++ni) {
                float2 v;
                v.x = f2tf32(acc[mi][ni][half * 2 + 0]);
                v.y = f2tf32(acc[mi][ni][half * 2 + 1]);
                __stcs((float2*)(base + ni * 8), v);
            }
        }
    }
}

// ============================================================================
// gemm2: z[p][n] = sum_e A[p][e]*Wo[e][n] + bias -> rmsnorm(g_out)
// 128x128x1024, 3-stage ring, 512 thr.
// ============================================================================
__global__ __launch_bounds__(512, 2)
void gemm2_kernel(const float* __restrict__ bo, const float* __restrict__ gout,
                  float* __restrict__ out) {
    extern __shared__ float sm[];
    const int tid = threadIdx.x, w = tid >> 5, l = tid & 31;
    const int mw = w >> 2, nw = w & 3, lg = l >> 2, lm4 = l & 3;
    const int p_base = blockIdx.x * 128;
    const uint32_t smb = smem_u32(sm);
    const LdsmAddrs ad = ldsm_prep(w, l);

    float acc[2][4][4] = {};

    int srow[2], sq[2];
    uint32_t sdst[2];
#pragma unroll
    for (int v = 0; v < 2; ++v) {
        const int fl = v * 512 + tid;
        srow[v] = fl >> 3;
        sq[v]   = fl & 7;
        sdst[v] = (uint32_t)((srow[v] * 8 + (sq[v] ^ (srow[v] & 7))) * 16);
    }

#define G2_STAGE(ks, buf) do {                                                  \
    const uint32_t bofs = smb + (uint32_t)(buf) * 32768u;                       \
    _Pragma("unroll")                                                           \
    for (int v = 0; v < 2; ++v) {                                               \
        const float* sA = g_a + (size_t)(p_base + srow[v]) * 1024 + (ks) * 32 + sq[v] * 4; \
        const int fl = v * 512 + tid;                                           \
        const float* sB = g_wo + (ks) * 4096 + fl * 4;                          \
        CP_ASYNC16(bofs + sdst[v], sA);                                         \
        CP_ASYNC16(bofs + 16384 + (uint32_t)(fl * 16), sB);                     \
    }                                                                           \
    CP_COMMIT();                                                                \
} while (0)

    G2_STAGE(0, 0);
    G2_STAGE(1, 1);
#pragma unroll 4
    for (int ks = 0; ks < 32; ++ks) {
        if (ks + 1 < 32) CP_WAIT1(); else CP_WAIT0();
        __syncthreads();
        if (ks + 2 < 32) G2_STAGE(ks + 2, (ks + 2) % 3);
        mma_chunk(smb + (uint32_t)(ks % 3) * 32768u, ad, acc);
    }
    __syncthreads();

    float* Ds = sm;
#pragma unroll
    for (int mi = 0; mi < 2; ++mi) {
        const int r0 = mw * 32 + mi * 16 + lg;
#pragma unroll
        for (int ni = 0; ni < 4; ++ni) {
            const int c0 = nw * 32 + ni * 8 + lm4 * 2;
            *(float2*)(Ds + r0 * 132 + c0)       = make_float2(acc[mi][ni][0], acc[mi][ni][1]);
            *(float2*)(Ds + (r0 + 8) * 132 + c0) = make_float2(acc[mi][ni][2], acc[mi][ni][3]);
        }
    }
    __syncthreads();

    // bias + rmsnorm: 4 threads per row (32 z each), quad shfl reduce
    const int row = tid >> 2, q4 = tid & 3;
    const float* rp = Ds + row * 132 + q4 * 32;
    float fv[32];
    float ssq = 0.0f;
#pragma unroll
    for (int q = 0; q < 8; ++q) {
        float4 v = *(const float4*)(rp + q * 4);
        const float4 bb = __ldg((const float4*)(bo + q4 * 32 + q * 4));
        fv[q * 4 + 0] = v.x + bb.x;
        fv[q * 4 + 1] = v.y + bb.y;
        fv[q * 4 + 2] = v.z + bb.z;
        fv[q * 4 + 3] = v.w + bb.w;
        ssq = fmaf(fv[q*4+0], fv[q*4+0], ssq);
        ssq = fmaf(fv[q*4+1], fv[q*4+1], ssq);
        ssq = fmaf(fv[q*4+2], fv[q*4+2], ssq);
        ssq = fmaf(fv[q*4+3], fv[q*4+3], ssq);
    }
    ssq += __shfl_xor_sync(~0u, ssq, 1);
    ssq += __shfl_xor_sync(~0u, ssq, 2);
    const float sc = rsqrtf(ssq * (1.0f / 128.0f) + EPSV);
    float* op = out + (size_t)(p_base + row) * 128 + q4 * 32;
#pragma unroll
    for (int q = 0; q < 8; ++q) {
        const float4 gg = __ldg((const float4*)(gout + q4 * 32 + q * 4));
        float4 v;
        v.x = fv[q * 4 + 0] * sc * gg.x;
        v.y = fv[q * 4 + 1] * sc * gg.y;
        v.z = fv[q * 4 + 2] * sc * gg.z;
        v.w = fv[q * 4 + 3] * sc * gg.w;
        *(float4*)(op + q * 4) = v;
    }
}

// ============================================================================
extern "C" void kernel_launch(void* const* d_in, const int* in_sizes, int n_in,
                              void* d_out, int out_size) {
    const float* m    = (const float*)d_in[0];
    const float* g_in = (const float*)d_in[1];
    const float* Wq   = (const float*)d_in[2];
    const float* bq   = (const float*)d_in[3];
    const float* Wk   = (const float*)d_in[4];
    const float* bk   = (const float*)d_in[5];
    const float* Wo   = (const float*)d_in[6];
    const float* bo   = (const float*)d_in[7];
    const float* gout = (const float*)d_in[8];
    float* out = (float*)d_out;

    cudaFuncSetAttribute(proj_kernel,  cudaFuncAttributeMaxDynamicSharedMemorySize, 98304);
    cudaFuncSetAttribute(gemm1_kernel, cudaFuncAttributeMaxDynamicSharedMemorySize, 98304);
    cudaFuncSetAttribute(gemm2_kernel, cudaFuncAttributeMaxDynamicSharedMemorySize, 98304);

    proj_kernel<<<(256 * 384) / 32, 256, 98304>>>(m, g_in, Wq, bq, Wk, bk);
    wot_kernel<<<32, 128>>>(Wo);
    gemm1_kernel<<<dim3(96, 96), 512, 98304>>>();
    gemm2_kernel<<<1152, 512, 98304>>>(bo, gout, out);
}

// round 10
// speedup vs baseline: 1.1104x; 1.1104x over previous
#include <cuda_runtime.h>
#include <cstdint>
#include <cstddef>

#define EPSV 1e-5f

// g_q/g_k: [(s*32+c)*256 + b]  — GEMM1 operand rows (m=(s,c)), K(=b)-contiguous
__device__ float g_q[384 * 32 * 256];
__device__ float g_k[384 * 32 * 256];
// g_wo: 32 k-slices, each the ready smem image: [n=128][32 floats, XOR-swizzled]
__device__ float g_wo[32 * 4096];
// g_a: [p = i*384+j][e = c*32+d]  row-major — GEMM2 A operand
__device__ float g_a[150994944];  // 147456 * 1024 floats = 604 MB

// ---------------- helpers ----------------
__device__ __forceinline__ uint32_t smem_u32(const void* p) {
    uint32_t a;
    asm("{ .reg .u64 t; cvta.to.shared.u64 t, %1; cvt.u32.u64 %0, t; }" : "=r"(a) : "l"(p));
    return a;
}
__device__ __forceinline__ float f2tf32(float x) {
    uint32_t r;
    asm("cvt.rna.tf32.f32 %0, %1;" : "=r"(r) : "f"(x));
    return __uint_as_float(r);
}
#define CP_ASYNC16(dst, src) \
    asm volatile("cp.async.cg.shared.global [%0], [%1], 16;" :: "r"(dst), "l"(src))
#define CP_COMMIT() asm volatile("cp.async.commit_group;")
#define CP_WAIT1()  asm volatile("cp.async.wait_group 1;")
#define CP_WAIT0()  asm volatile("cp.async.wait_group 0;")

#define LDSM_X4(r0, r1, r2, r3, addr) \
    asm volatile("ldmatrix.sync.aligned.m8n8.x4.shared.b16 {%0,%1,%2,%3}, [%4];" \
                 : "=r"(r0), "=r"(r1), "=r"(r2), "=r"(r3) : "r"(addr))

__device__ __forceinline__ void mma_tf32(float* d, uint32_t a0, uint32_t a1,
                                         uint32_t a2, uint32_t a3,
                                         uint32_t b0, uint32_t b1) {
    asm volatile(
        "mma.sync.aligned.m16n8k8.row.col.f32.tf32.tf32.f32 "
        "{%0,%1,%2,%3}, {%4,%5,%6,%7}, {%8,%9}, {%0,%1,%2,%3};"
        : "+f"(d[0]), "+f"(d[1]), "+f"(d[2]), "+f"(d[3])
        : "r"(a0), "r"(a1), "r"(a2), "r"(a3), "r"(b0), "r"(b1));
}

// ============================================================================
// proj: rmsnorm(m)*g_in -> q/k projections -> tf32-rounded transposed store
// ============================================================================
__global__ __launch_bounds__(256, 2)
void proj_kernel(const float* __restrict__ m, const float* __restrict__ g_in,
                 const float* __restrict__ Wq, const float* __restrict__ bq,
                 const float* __restrict__ Wk, const float* __restrict__ bk)
{
    extern __shared__ float sm[];
    float* Wq_s = sm;
    float* Wk_s = sm + 8192;
    float* mn_s = sm + 16384;
    const int tid = threadIdx.x, warp = tid >> 5, lane = tid & 31;
    const float4* Wq4 = (const float4*)Wq;
    const float4* Wk4 = (const float4*)Wk;
#pragma unroll
    for (int v = 0; v < 8; ++v) {
        ((float4*)Wq_s)[v * 256 + tid] = Wq4[v * 256 + tid];
        ((float4*)Wk_s)[v * 256 + tid] = Wk4[v * 256 + tid];
    }
    const int rb = (blockIdx.x * 8 + warp) * 4;
    float* mw = mn_s + warp * 1024;
    const float4 gi0 = ((const float4*)g_in)[lane * 2];
    const float4 gi1 = ((const float4*)g_in)[lane * 2 + 1];
    float vals[4][8], ssum[4];
#pragma unroll
    for (int r = 0; r < 4; ++r) {
        const float4* mp = (const float4*)(m + (size_t)(rb + r) * 256);
        float4 a = mp[lane * 2], b = mp[lane * 2 + 1];
        vals[r][0] = a.x; vals[r][1] = a.y; vals[r][2] = a.z; vals[r][3] = a.w;
        vals[r][4] = b.x; vals[r][5] = b.y; vals[r][6] = b.z; vals[r][7] = b.w;
        ssum[r] = a.x*a.x + a.y*a.y + a.z*a.z + a.w*a.w
                + b.x*b.x + b.y*b.y + b.z*b.z + b.w*b.w;
    }
#pragma unroll
    for (int r = 0; r < 4; ++r) {
        float s = ssum[r];
#pragma unroll
        for (int o = 16; o >= 1; o >>= 1) s += __shfl_xor_sync(~0u, s, o);
        const float sc = rsqrtf(s * (1.0f / 256.0f) + EPSV);
        float4 o0, o1;
        o0.x = vals[r][0]*sc*gi0.x; o0.y = vals[r][1]*sc*gi0.y;
        o0.z = vals[r][2]*sc*gi0.z; o0.w = vals[r][3]*sc*gi0.w;
        o1.x = vals[r][4]*sc*gi1.x; o1.y = vals[r][5]*sc*gi1.y;
        o1.z = vals[r][6]*sc*gi1.z; o1.w = vals[r][7]*sc*gi1.w;
        ((float4*)(mw + r * 256))[lane * 2]     = o0;
        ((float4*)(mw + r * 256))[lane * 2 + 1] = o1;
    }
    __syncthreads();
    float aq[4], ak[4];
    const float bqv = __ldg(bq + lane), bkv = __ldg(bk + lane);
#pragma unroll
    for (int r = 0; r < 4; ++r) { aq[r] = bqv; ak[r] = bkv; }
#pragma unroll 4
    for (int mm = 0; mm < 256; ++mm) {
        const float wq = Wq_s[mm * 32 + lane], wk = Wk_s[mm * 32 + lane];
#pragma unroll
        for (int r = 0; r < 4; ++r) {
            const float x = mw[r * 256 + mm];
            aq[r] = fmaf(x, wq, aq[r]);
            ak[r] = fmaf(x, wk, ak[r]);
        }
    }
#pragma unroll
    for (int r = 0; r < 4; ++r) {
        const int row = rb + r, b = row / 384, s = row - b * 384;
        g_q[(size_t)(s * 32 + lane) * 256 + b] = f2tf32(aq[r]);
        g_k[(size_t)(s * 32 + lane) * 256 + b] = f2tf32(ak[r]);
    }
}

// ============================================================================
// wot: Wo[e=ks*32+kk][z=n] -> g_wo[ks][n*32 + swiz(kk,n)] (tf32-rounded)
// ============================================================================
__global__ void wot_kernel(const float* __restrict__ Wo) {
    const int ks = blockIdx.x, n = threadIdx.x;
    float* dst = g_wo + ks * 4096 + n * 32;
    const int n7 = n & 7;
#pragma unroll
    for (int kk = 0; kk < 32; ++kk) {
        const float v = f2tf32(__ldg(Wo + (size_t)(ks * 32 + kk) * 128 + n));
        dst[(((kk >> 2) ^ n7) << 2) | (kk & 3)] = v;
    }
}

// ============================================================================
// gemm1 (exact R7 champion): 256 thr, 8 warps 2x4, warp tile 64x32,
// 3-stage ring, direct register->global scatter epilogue.
// ============================================================================
struct LdsmAddrs { uint32_t a[4]; uint32_t b[2]; };

__device__ __forceinline__ LdsmAddrs ldsm_prep(int w, int l) {
    const int mw = w >> 2, nw = w & 3;
    const int r7 = l & 7;
    LdsmAddrs o;
    const int kbitA = (l >> 4) & 1;
    const int rhiA  = (l >> 3) & 1;
#pragma unroll
    for (int mi = 0; mi < 4; ++mi) {
        const int row = mw * 64 + mi * 16 + rhiA * 8 + r7;
        o.a[mi] = (uint32_t)(row * 128 + ((r7 ^ kbitA) << 4));
    }
    const int kbitB = (l >> 3) & 1;
    const int rhiB  = (l >> 4) & 1;
#pragma unroll
    for (int nip = 0; nip < 2; ++nip) {
        const int row = nw * 32 + nip * 16 + rhiB * 8 + r7;
        o.b[nip] = (uint32_t)(16384 + row * 128 + ((r7 ^ kbitB) << 4));
    }
    return o;
}

__device__ __forceinline__ void mma_chunk(uint32_t stage, const LdsmAddrs& ad,
                                          float acc[4][4][4]) {
#pragma unroll
    for (int s = 0; s < 4; ++s) {
        const uint32_t sx = (uint32_t)(s << 5);
        uint32_t b0[4], b1[4];
        LDSM_X4(b0[0], b1[0], b0[1], b1[1], stage + (ad.b[0] ^ sx));
        LDSM_X4(b0[2], b1[2], b0[3], b1[3], stage + (ad.b[1] ^ sx));
#pragma unroll
        for (int mi = 0; mi < 4; ++mi) {
            uint32_t A0, A1, A2, A3;
            LDSM_X4(A0, A1, A2, A3, stage + (ad.a[mi] ^ sx));
#pragma unroll
            for (int ni = 0; ni < 4; ++ni)
                mma_tf32(acc[mi][ni], A0, A1, A2, A3, b0[ni], b1[ni]);
        }
    }
}

__global__ __launch_bounds__(256, 2)
void gemm1_kernel() {
    extern __shared__ float sm[];
    const int tid = threadIdx.x, w = tid >> 5, l = tid & 31;
    const int mw = w >> 2, nw = w & 3, lg = l >> 2, lm4 = l & 3;
    const int irow = blockIdx.y * 128, jrow = blockIdx.x * 128;
    const uint32_t smb = smem_u32(sm);
    const LdsmAddrs ad = ldsm_prep(w, l);

    float acc[4][4][4] = {};

    int srow[4], sq[4];
    uint32_t sdst[4];
#pragma unroll
    for (int v = 0; v < 4; ++v) {
        const int fl = v * 256 + tid;
        srow[v] = fl >> 3;
        sq[v]   = fl & 7;
        sdst[v] = (uint32_t)((srow[v] * 8 + (sq[v] ^ (srow[v] & 7))) * 16);
    }

#define G1_STAGE(ks, buf) do {                                                  \
    const uint32_t bofs = smb + (uint32_t)(buf) * 32768u;                       \
    _Pragma("unroll")                                                           \
    for (int v = 0; v < 4; ++v) {                                               \
        const float* sA = g_q + (size_t)(irow + srow[v]) * 256 + (ks) * 32 + sq[v] * 4; \
        const float* sB = g_k + (size_t)(jrow + srow[v]) * 256 + (ks) * 32 + sq[v] * 4; \
        CP_ASYNC16(bofs + sdst[v], sA);                                         \
        CP_ASYNC16(bofs + 16384 + sdst[v], sB);                                 \
    }                                                                           \
    CP_COMMIT();                                                                \
} while (0)

    G1_STAGE(0, 0);
    G1_STAGE(1, 1);
#pragma unroll
    for (int ks = 0; ks < 8; ++ks) {
        if (ks + 1 < 8) CP_WAIT1(); else CP_WAIT0();
        __syncthreads();
        if (ks + 2 < 8) G1_STAGE(ks + 2, (ks + 2) % 3);
        mma_chunk(smb + (uint32_t)(ks % 3) * 32768u, ad, acc);
    }

    const int j = blockIdx.x * 4 + nw;
#pragma unroll
    for (int mi = 0; mi < 4; ++mi) {
        const int r_lo = mw * 64 + mi * 16 + lg;
#pragma unroll
        for (int half = 0; half < 2; ++half) {
            const int r = r_lo + half * 8;
            const int i = blockIdx.y * 4 + (r >> 5);
            const int c = r & 31;
            float* base = g_a + (size_t)(i * 384 + j) * 1024 + c * 32 + lm4 * 2;
#pragma unroll
            for (int ni = 0; ni < 4; ++ni) {
                float2 v;
                v.x = f2tf32(acc[mi][ni][half * 2 + 0]);
                v.y = f2tf32(acc[mi][ni][half * 2 + 1]);
                __stcs((float2*)(base + ni * 8), v);
            }
        }
    }
}

// ============================================================================
// gemm2: 128 thr, 4 warps 2x2, warp tile 64x64 (128B smem per mma),
// 2-stage ring + trailing sync, 3 CTAs/SM. Epilogue: bias+rmsnorm, coalesced.
// ============================================================================
__global__ __launch_bounds__(128, 3)
void gemm2_kernel(const float* __restrict__ bo, const float* __restrict__ gout,
                  float* __restrict__ out) {
    extern __shared__ float sm[];
    const int tid = threadIdx.x, w = tid >> 5, l = tid & 31;
    const int mw = w >> 1, nw = w & 1, lg = l >> 2, lm4 = l & 3;
    const int p_base = blockIdx.x * 128;
    const uint32_t smb = smem_u32(sm);

    // ldmatrix addresses: A tiles mi 0..3 (rows mw*64+mi*16), B tiles nip 0..3
    const int r7 = l & 7;
    const int kbitA = (l >> 4) & 1, rhiA = (l >> 3) & 1;
    const int kbitB = (l >> 3) & 1, rhiB = (l >> 4) & 1;
    uint32_t aOff[4], bOff[4];
#pragma unroll
    for (int mi = 0; mi < 4; ++mi) {
        const int row = mw * 64 + mi * 16 + rhiA * 8 + r7;
        aOff[mi] = (uint32_t)(row * 128 + ((r7 ^ kbitA) << 4));
    }
#pragma unroll
    for (int nip = 0; nip < 4; ++nip) {
        const int row = nw * 64 + nip * 16 + rhiB * 8 + r7;
        bOff[nip] = (uint32_t)(16384 + row * 128 + ((r7 ^ kbitB) << 4));
    }

    float acc[4][8][4] = {};

    int srow[8], sq[8];
    uint32_t sdst[8];
#pragma unroll
    for (int v = 0; v < 8; ++v) {
        const int fl = v * 128 + tid;
        srow[v] = fl >> 3;
        sq[v]   = fl & 7;
        sdst[v] = (uint32_t)((srow[v] * 8 + (sq[v] ^ (srow[v] & 7))) * 16);
    }

#define G2_STAGE(ks, buf) do {                                                  \
    const uint32_t bofs = smb + (uint32_t)(buf) * 32768u;                       \
    _Pragma("unroll")                                                           \
    for (int v = 0; v < 8; ++v) {                                               \
        const float* sA = g_a + (size_t)(p_base + srow[v]) * 1024 + (ks) * 32 + sq[v] * 4; \
        CP_ASYNC16(bofs + sdst[v], sA);                                         \
        const int fl = v * 128 + tid;                                           \
        const float* sB = g_wo + (ks) * 4096 + fl * 4;                          \
        CP_ASYNC16(bofs + 16384 + (uint32_t)(fl * 16), sB);                     \
    }                                                                           \
    CP_COMMIT();                                                                \
} while (0)

    G2_STAGE(0, 0);
    for (int ks = 0; ks < 32; ++ks) {
        if (ks + 1 < 32) { G2_STAGE(ks + 1, (ks + 1) & 1); CP_WAIT1(); }
        else             { CP_WAIT0(); }
        __syncthreads();
        const uint32_t stage = smb + (uint32_t)(ks & 1) * 32768u;
#pragma unroll
        for (int s = 0; s < 4; ++s) {
            const uint32_t sx = (uint32_t)(s << 5);
            uint32_t b0[8], b1[8];
#pragma unroll
            for (int nip = 0; nip < 4; ++nip)
                LDSM_X4(b0[2*nip], b1[2*nip], b0[2*nip+1], b1[2*nip+1],
                        stage + (bOff[nip] ^ sx));
#pragma unroll
            for (int mi = 0; mi < 4; ++mi) {
                uint32_t A0, A1, A2, A3;
                LDSM_X4(A0, A1, A2, A3, stage + (aOff[mi] ^ sx));
#pragma unroll
                for (int ni = 0; ni < 8; ++ni)
                    mma_tf32(acc[mi][ni], A0, A1, A2, A3, b0[ni], b1[ni]);
            }
        }
        __syncthreads();   // all warps done with this buffer before re-stage
    }

    // epilogue: acc -> Ds[128][132], then bias + rmsnorm + coalesced store
    float* Ds = sm;
#pragma unroll
    for (int mi = 0; mi < 4; ++mi) {
        const int r0 = mw * 64 + mi * 16 + lg;
#pragma unroll
        for (int ni = 0; ni < 8; ++ni) {
            const int c0 = nw * 64 + ni * 8 + lm4 * 2;
            *(float2*)(Ds + r0 * 132 + c0)       = make_float2(acc[mi][ni][0], acc[mi][ni][1]);
            *(float2*)(Ds + (r0 + 8) * 132 + c0) = make_float2(acc[mi][ni][2], acc[mi][ni][3]);
        }
    }
    __syncthreads();

    // pass 1: one thread per row — bias, ssq, write biased back, stash scale
    float* scA = sm + 16896;   // after Ds (max idx 16895)
    {
        float* rp = Ds + tid * 132;
        float ssq = 0.0f;
        for (int q = 0; q < 32; ++q) {
            float4 v = *(float4*)(rp + q * 4);
            const float4 bb = __ldg((const float4*)(bo + q * 4));
            v.x += bb.x; v.y += bb.y; v.z += bb.z; v.w += bb.w;
            ssq = fmaf(v.x, v.x, ssq);
            ssq = fmaf(v.y, v.y, ssq);
            ssq = fmaf(v.z, v.z, ssq);
            ssq = fmaf(v.w, v.w, ssq);
            *(float4*)(rp + q * 4) = v;
        }
        scA[tid] = rsqrtf(ssq * (1.0f / 128.0f) + EPSV);
    }
    __syncthreads();

    // pass 2: coalesced writes (32 consecutive threads cover one row-chunk)
#pragma unroll 4
    for (int v = 0; v < 32; ++v) {
        const int fl = v * 128 + tid;
        const int row = fl >> 5, col = (fl & 31) * 4;
        float4 vv = *(float4*)(Ds + row * 132 + col);
        const float sc = scA[row];
        const float4 gg = __ldg((const float4*)(gout + col));
        vv.x *= sc * gg.x; vv.y *= sc * gg.y;
        vv.z *= sc * gg.z; vv.w *= sc * gg.w;
        *(float4*)(out + (size_t)(p_base + row) * 128 + col) = vv;
    }
}

// ============================================================================
extern "C" void kernel_launch(void* const* d_in, const int* in_sizes, int n_in,
                              void* d_out, int out_size) {
    const float* m    = (const float*)d_in[0];
    const float* g_in = (const float*)d_in[1];
    const float* Wq   = (const float*)d_in[2];
    const float* bq   = (const float*)d_in[3];
    const float* Wk   = (const float*)d_in[4];
    const float* bk   = (const float*)d_in[5];
    const float* Wo   = (const float*)d_in[6];
    const float* bo   = (const float*)d_in[7];
    const float* gout = (const float*)d_in[8];
    float* out = (float*)d_out;

    cudaFuncSetAttribute(proj_kernel,  cudaFuncAttributeMaxDynamicSharedMemorySize, 98304);
    cudaFuncSetAttribute(gemm1_kernel, cudaFuncAttributeMaxDynamicSharedMemorySize, 98304);
    cudaFuncSetAttribute(gemm2_kernel, cudaFuncAttributeMaxDynamicSharedMemorySize, 69632);

    proj_kernel<<<(256 * 384) / 32, 256, 98304>>>(m, g_in, Wq, bq, Wk, bk);
    wot_kernel<<<32, 128>>>(Wo);
    gemm1_kernel<<<dim3(96, 96), 256, 98304>>>();
    gemm2_kernel<<<1152, 128, 69632>>>(bo, gout, out);
}

// round 11
// speedup vs baseline: 1.7555x; 1.5810x over previous
#include <cuda_runtime.h>
#include <cuda_fp16.h>
#include <cstdint>
#include <cstddef>

#define EPSV 1e-5f

// g_q/g_k: fp16 [(s*32+c)*256 + b] — GEMM1 operand rows, K(=b)-contiguous
__device__ __half g_q[384 * 32 * 256];
__device__ __half g_k[384 * 32 * 256];
// g_wo: fp16, 16 k-chunks, each preswizzled smem image [n=128][64 halfs]
__device__ __half g_wo[16 * 128 * 64];
// g_a: fp16 [p = i*384+j][e = c*32+d] row-major — GEMM2 A operand (302 MB)
__device__ __half g_a[150994944];

// ---------------- helpers ----------------
__device__ __forceinline__ uint32_t smem_u32(const void* p) {
    uint32_t a;
    asm("{ .reg .u64 t; cvta.to.shared.u64 t, %1; cvt.u32.u64 %0, t; }" : "=r"(a) : "l"(p));
    return a;
}
#define CP_ASYNC16(dst, src) \
    asm volatile("cp.async.cg.shared.global [%0], [%1], 16;" :: "r"(dst), "l"(src))
#define CP_COMMIT() asm volatile("cp.async.commit_group;")
#define CP_WAIT1()  asm volatile("cp.async.wait_group 1;")
#define CP_WAIT0()  asm volatile("cp.async.wait_group 0;")

#define LDSM_X4(r0, r1, r2, r3, addr) \
    asm volatile("ldmatrix.sync.aligned.m8n8.x4.shared.b16 {%0,%1,%2,%3}, [%4];" \
                 : "=r"(r0), "=r"(r1), "=r"(r2), "=r"(r3) : "r"(addr))

__device__ __forceinline__ void mma_f16(float* d, uint32_t a0, uint32_t a1,
                                        uint32_t a2, uint32_t a3,
                                        uint32_t b0, uint32_t b1) {
    asm volatile(
        "mma.sync.aligned.m16n8k16.row.col.f32.f16.f16.f32 "
        "{%0,%1,%2,%3}, {%4,%5,%6,%7}, {%8,%9}, {%0,%1,%2,%3};"
        : "+f"(d[0]), "+f"(d[1]), "+f"(d[2]), "+f"(d[3])
        : "r"(a0), "r"(a1), "r"(a2), "r"(a3), "r"(b0), "r"(b1));
}

// ============================================================================
// proj: rmsnorm(m)*g_in -> q/k projections -> fp16 transposed store
// ============================================================================
__global__ __launch_bounds__(256, 2)
void proj_kernel(const float* __restrict__ m, const float* __restrict__ g_in,
                 const float* __restrict__ Wq, const float* __restrict__ bq,
                 const float* __restrict__ Wk, const float* __restrict__ bk)
{
    extern __shared__ float sm[];
    float* Wq_s = sm;
    float* Wk_s = sm + 8192;
    float* mn_s = sm + 16384;
    const int tid = threadIdx.x, warp = tid >> 5, lane = tid & 31;
    const float4* Wq4 = (const float4*)Wq;
    const float4* Wk4 = (const float4*)Wk;
#pragma unroll
    for (int v = 0; v < 8; ++v) {
        ((float4*)Wq_s)[v * 256 + tid] = Wq4[v * 256 + tid];
        ((float4*)Wk_s)[v * 256 + tid] = Wk4[v * 256 + tid];
    }
    const int rb = (blockIdx.x * 8 + warp) * 4;
    float* mw = mn_s + warp * 1024;
    const float4 gi0 = ((const float4*)g_in)[lane * 2];
    const float4 gi1 = ((const float4*)g_in)[lane * 2 + 1];
    float vals[4][8], ssum[4];
#pragma unroll
    for (int r = 0; r < 4; ++r) {
        const float4* mp = (const float4*)(m + (size_t)(rb + r) * 256);
        float4 a = mp[lane * 2], b = mp[lane * 2 + 1];
        vals[r][0] = a.x; vals[r][1] = a.y; vals[r][2] = a.z; vals[r][3] = a.w;
        vals[r][4] = b.x; vals[r][5] = b.y; vals[r][6] = b.z; vals[r][7] = b.w;
        ssum[r] = a.x*a.x + a.y*a.y + a.z*a.z + a.w*a.w
                + b.x*b.x + b.y*b.y + b.z*b.z + b.w*b.w;
    }
#pragma unroll
    for (int r = 0; r < 4; ++r) {
        float s = ssum[r];
#pragma unroll
        for (int o = 16; o >= 1; o >>= 1) s += __shfl_xor_sync(~0u, s, o);
        const float sc = rsqrtf(s * (1.0f / 256.0f) + EPSV);
        float4 o0, o1;
        o0.x = vals[r][0]*sc*gi0.x; o0.y = vals[r][1]*sc*gi0.y;
        o0.z = vals[r][2]*sc*gi0.z; o0.w = vals[r][3]*sc*gi0.w;
        o1.x = vals[r][4]*sc*gi1.x; o1.y = vals[r][5]*sc*gi1.y;
        o1.z = vals[r][6]*sc*gi1.z; o1.w = vals[r][7]*sc*gi1.w;
        ((float4*)(mw + r * 256))[lane * 2]     = o0;
        ((float4*)(mw + r * 256))[lane * 2 + 1] = o1;
    }
    __syncthreads();
    float aq[4], ak[4];
    const float bqv = __ldg(bq + lane), bkv = __ldg(bk + lane);
#pragma unroll
    for (int r = 0; r < 4; ++r) { aq[r] = bqv; ak[r] = bkv; }
#pragma unroll 4
    for (int mm = 0; mm < 256; ++mm) {
        const float wq = Wq_s[mm * 32 + lane], wk = Wk_s[mm * 32 + lane];
#pragma unroll
        for (int r = 0; r < 4; ++r) {
            const float x = mw[r * 256 + mm];
            aq[r] = fmaf(x, wq, aq[r]);
            ak[r] = fmaf(x, wk, ak[r]);
        }
    }
#pragma unroll
    for (int r = 0; r < 4; ++r) {
        const int row = rb + r, b = row / 384, s = row - b * 384;
        g_q[(size_t)(s * 32 + lane) * 256 + b] = __float2half(aq[r]);
        g_k[(size_t)(s * 32 + lane) * 256 + b] = __float2half(ak[r]);
    }
}

// ============================================================================
// wot: Wo[e=ks*64+kk][z=n] -> g_wo[ks][n*64 + swz(kk,n)]  (fp16)
// swz: 16B unit (kk>>3) XOR (n&7), within-unit kk&7.
// ============================================================================
__global__ void wot_kernel(const float* __restrict__ Wo) {
    const int ks = blockIdx.x, n = threadIdx.x;
    __half* dst = g_wo + ks * 8192 + n * 64;
    const int n7 = n & 7;
#pragma unroll
    for (int kk = 0; kk < 64; ++kk) {
        const float v = __ldg(Wo + (size_t)(ks * 64 + kk) * 128 + n);
        dst[(((kk >> 3) ^ n7) << 3) | (kk & 7)] = __float2half(v);
    }
}

// ============================================================================
// gemm1: 256 thr, 8 warps 2x4, warp tile 64x32, fp16 m16n8k16.
// 128x128 tile, K=256 in 4 chunks of 64; 3-stage ring; direct scatter.
// Stage layout: A 128 rows x 128B (swizzled) @0, B same @16384.
// ============================================================================
__global__ __launch_bounds__(256, 2)
void gemm1_kernel() {
    extern __shared__ float sm[];
    const int tid = threadIdx.x, w = tid >> 5, l = tid & 31;
    const int mw = w >> 2, nw = w & 3, lg = l >> 2, lm4 = l & 3;
    const int irow = blockIdx.y * 128, jrow = blockIdx.x * 128;
    const uint32_t smb = smem_u32(sm);

    const int r7 = l & 7;
    const int rhiA = (l >> 3) & 1, kbA = (l >> 4) & 1;
    const int rhiB = (l >> 4) & 1, kbB = (l >> 3) & 1;
    uint32_t aRow[4], bRow[2];
#pragma unroll
    for (int mi = 0; mi < 4; ++mi)
        aRow[mi] = (uint32_t)((mw * 64 + mi * 16 + rhiA * 8 + r7) * 128);
#pragma unroll
    for (int nip = 0; nip < 2; ++nip)
        bRow[nip] = (uint32_t)(16384 + (nw * 32 + nip * 16 + rhiB * 8 + r7) * 128);

    float acc[4][4][4] = {};

    int srow[4], sq[4];
    uint32_t sdst[4];
#pragma unroll
    for (int v = 0; v < 4; ++v) {
        const int fl = v * 256 + tid;       // 1024 units per operand
        srow[v] = fl >> 3;
        sq[v]   = fl & 7;
        sdst[v] = (uint32_t)((srow[v] * 8 + (sq[v] ^ (srow[v] & 7))) * 16);
    }

#define G1_STAGE(ks, buf) do {                                                  \
    const uint32_t bofs = smb + (uint32_t)(buf) * 32768u;                       \
    _Pragma("unroll")                                                           \
    for (int v = 0; v < 4; ++v) {                                               \
        const __half* sA = g_q + (size_t)(irow + srow[v]) * 256 + (ks) * 64 + sq[v] * 8; \
        const __half* sB = g_k + (size_t)(jrow + srow[v]) * 256 + (ks) * 64 + sq[v] * 8; \
        CP_ASYNC16(bofs + sdst[v], sA);                                         \
        CP_ASYNC16(bofs + 16384 + sdst[v], sB);                                 \
    }                                                                           \
    CP_COMMIT();                                                                \
} while (0)

    G1_STAGE(0, 0);
    G1_STAGE(1, 1);
#pragma unroll
    for (int ks = 0; ks < 4; ++ks) {
        if (ks + 1 < 4) CP_WAIT1(); else CP_WAIT0();
        __syncthreads();
        if (ks + 2 < 4) G1_STAGE(ks + 2, (ks + 2) % 3);
        const uint32_t stage = smb + (uint32_t)(ks % 3) * 32768u;
#pragma unroll
        for (int s = 0; s < 4; ++s) {       // 4 k16-steps per 64-k chunk
            const uint32_t uA = (uint32_t)((((s << 1) | kbA) ^ r7) << 4);
            const uint32_t uB = (uint32_t)((((s << 1) | kbB) ^ r7) << 4);
            uint32_t b0[4], b1[4];
            LDSM_X4(b0[0], b1[0], b0[1], b1[1], stage + bRow[0] + uB);
            LDSM_X4(b0[2], b1[2], b0[3], b1[3], stage + bRow[1] + uB);
#pragma unroll
            for (int mi = 0; mi < 4; ++mi) {
                uint32_t A0, A1, A2, A3;
                LDSM_X4(A0, A1, A2, A3, stage + aRow[mi] + uA);
#pragma unroll
                for (int ni = 0; ni < 4; ++ni)
                    mma_f16(acc[mi][ni], A0, A1, A2, A3, b0[ni], b1[ni]);
            }
        }
    }

    // direct epilogue: fp16 half2 scatter into g_a
    const int j = blockIdx.x * 4 + nw;
#pragma unroll
    for (int mi = 0; mi < 4; ++mi) {
        const int r_lo = mw * 64 + mi * 16 + lg;
#pragma unroll
        for (int half = 0; half < 2; ++half) {
            const int r = r_lo + half * 8;
            const int i = blockIdx.y * 4 + (r >> 5);
            const int c = r & 31;
            __half* base = g_a + (size_t)(i * 384 + j) * 1024 + c * 32 + lm4 * 2;
#pragma unroll
            for (int ni = 0; ni < 4; ++ni) {
                __half2 v = __floats2half2_rn(acc[mi][ni][half * 2 + 0],
                                              acc[mi][ni][half * 2 + 1]);
                __stcs((__half2*)(base + ni * 8), v);
            }
        }
    }
}

// ============================================================================
// gemm2: 128 thr, 4 warps 2x2, warp tile 64x64, fp16 m16n8k16.
// 128x128 tile, K=1024 in 16 chunks of 64; 2-stage ring; rmsnorm epilogue.
// ============================================================================
__global__ __launch_bounds__(128, 3)
void gemm2_kernel(const float* __restrict__ bo, const float* __restrict__ gout,
                  float* __restrict__ out) {
    extern __shared__ float sm[];
    const int tid = threadIdx.x, w = tid >> 5, l = tid & 31;
    const int mw = w >> 1, nw = w & 1, lg = l >> 2, lm4 = l & 3;
    const int p_base = blockIdx.x * 128;
    const uint32_t smb = smem_u32(sm);

    const int r7 = l & 7;
    const int rhiA = (l >> 3) & 1, kbA = (l >> 4) & 1;
    const int rhiB = (l >> 4) & 1, kbB = (l >> 3) & 1;
    uint32_t aRow[4], bRow[4];
#pragma unroll
    for (int mi = 0; mi < 4; ++mi)
        aRow[mi] = (uint32_t)((mw * 64 + mi * 16 + rhiA * 8 + r7) * 128);
#pragma unroll
    for (int nip = 0; nip < 4; ++nip)
        bRow[nip] = (uint32_t)(16384 + (nw * 64 + nip * 16 + rhiB * 8 + r7) * 128);

    float acc[4][8][4] = {};

    int srow[8], sq[8];
    uint32_t sdst[8];
#pragma unroll
    for (int v = 0; v < 8; ++v) {
        const int fl = v * 128 + tid;       // 1024 units per operand
        srow[v] = fl >> 3;
        sq[v]   = fl & 7;
        sdst[v] = (uint32_t)((srow[v] * 8 + (sq[v] ^ (srow[v] & 7))) * 16);
    }

#define G2_STAGE(ks, buf) do {                                                  \
    const uint32_t bofs = smb + (uint32_t)(buf) * 32768u;                       \
    _Pragma("unroll")                                                           \
    for (int v = 0; v < 8; ++v) {                                               \
        const __half* sA = g_a + (size_t)(p_base + srow[v]) * 1024 + (ks) * 64 + sq[v] * 8; \
        CP_ASYNC16(bofs + sdst[v], sA);                                         \
        const int fl = v * 128 + tid;                                           \
        const __half* sB = g_wo + (ks) * 8192 + fl * 8;                         \
        CP_ASYNC16(bofs + 16384 + (uint32_t)(fl * 16), sB);                     \
    }                                                                           \
    CP_COMMIT();                                                                \
} while (0)

    G2_STAGE(0, 0);
    for (int ks = 0; ks < 16; ++ks) {
        if (ks + 1 < 16) { G2_STAGE(ks + 1, (ks + 1) & 1); CP_WAIT1(); }
        else             { CP_WAIT0(); }
        __syncthreads();
        const uint32_t stage = smb + (uint32_t)(ks & 1) * 32768u;
#pragma unroll
        for (int s = 0; s < 4; ++s) {
            const uint32_t uA = (uint32_t)((((s << 1) | kbA) ^ r7) << 4);
            const uint32_t uB = (uint32_t)((((s << 1) | kbB) ^ r7) << 4);
            uint32_t b0[8], b1[8];
#pragma unroll
            for (int nip = 0; nip < 4; ++nip)
                LDSM_X4(b0[2*nip], b1[2*nip], b0[2*nip+1], b1[2*nip+1],
                        stage + bRow[nip] + uB);
#pragma unroll
            for (int mi = 0; mi < 4; ++mi) {
                uint32_t A0, A1, A2, A3;
                LDSM_X4(A0, A1, A2, A3, stage + aRow[mi] + uA);
#pragma unroll
                for (int ni = 0; ni < 8; ++ni)
                    mma_f16(acc[mi][ni], A0, A1, A2, A3, b0[ni], b1[ni]);
            }
        }
        __syncthreads();
    }

    // epilogue: acc -> Ds[128][132] -> bias + rmsnorm -> coalesced store
    float* Ds = sm;
#pragma unroll
    for (int mi = 0; mi < 4; ++mi) {
        const int r0 = mw * 64 + mi * 16 + lg;
#pragma unroll
        for (int ni = 0; ni < 8; ++ni) {
            const int c0 = nw * 64 + ni * 8 + lm4 * 2;
            *(float2*)(Ds + r0 * 132 + c0)       = make_float2(acc[mi][ni][0], acc[mi][ni][1]);
            *(float2*)(Ds + (r0 + 8) * 132 + c0) = make_float2(acc[mi][ni][2], acc[mi][ni][3]);
        }
    }
    __syncthreads();

    float* scA = sm + 16896;
    {
        float* rp = Ds + tid * 132;
        float ssq = 0.0f;
        for (int q = 0; q < 32; ++q) {
            float4 v = *(float4*)(rp + q * 4);
            const float4 bb = __ldg((const float4*)(bo + q * 4));
            v.x += bb.x; v.y += bb.y; v.z += bb.z; v.w += bb.w;
            ssq = fmaf(v.x, v.x, ssq);
            ssq = fmaf(v.y, v.y, ssq);
            ssq = fmaf(v.z, v.z, ssq);
            ssq = fmaf(v.w, v.w, ssq);
            *(float4*)(rp + q * 4) = v;
        }
        scA[tid] = rsqrtf(ssq * (1.0f / 128.0f) + EPSV);
    }
    __syncthreads();

#pragma unroll 4
    for (int v = 0; v < 32; ++v) {
        const int fl = v * 128 + tid;
        const int row = fl >> 5, col = (fl & 31) * 4;
        float4 vv = *(float4*)(Ds + row * 132 + col);
        const float sc = scA[row];
        const float4 gg = __ldg((const float4*)(gout + col));
        vv.x *= sc * gg.x; vv.y *= sc * gg.y;
        vv.z *= sc * gg.z; vv.w *= sc * gg.w;
        *(float4*)(out + (size_t)(p_base + row) * 128 + col) = vv;
    }
}

// ============================================================================
extern "C" void kernel_launch(void* const* d_in, const int* in_sizes, int n_in,
                              void* d_out, int out_size) {
    const float* m    = (const float*)d_in[0];
    const float* g_in = (const float*)d_in[1];
    const float* Wq   = (const float*)d_in[2];
    const float* bq   = (const float*)d_in[3];
    const float* Wk   = (const float*)d_in[4];
    const float* bk   = (const float*)d_in[5];
    const float* Wo   = (const float*)d_in[6];
    const float* bo   = (const float*)d_in[7];
    const float* gout = (const float*)d_in[8];
    float* out = (float*)d_out;

    cudaFuncSetAttribute(proj_kernel,  cudaFuncAttributeMaxDynamicSharedMemorySize, 98304);
    cudaFuncSetAttribute(gemm1_kernel, cudaFuncAttributeMaxDynamicSharedMemorySize, 98304);
    cudaFuncSetAttribute(gemm2_kernel, cudaFuncAttributeMaxDynamicSharedMemorySize, 69632);

    proj_kernel<<<(256 * 384) / 32, 256, 98304>>>(m, g_in, Wq, bq, Wk, bk);
    wot_kernel<<<16, 128>>>(Wo);
    gemm1_kernel<<<dim3(96, 96), 256, 98304>>>();
    gemm2_kernel<<<1152, 128, 69632>>>(bo, gout, out);
}